// round 5
// baseline (speedup 1.0000x reference)
#include <cuda_runtime.h>
#include <cuda_bf16.h>

// Problem constants
#define BATCH  4096
#define DIN    256
#define DOUT   256
#define NEXP   64

// Tiling
#define NTILE   128     // cols per block (2 blocks per expert)
#define MCHUNK  96      // rows per m-iteration (covers max expert count w.h.p.)
#define XSTRIDE 96      // transposed-x stride: store bank = r%32, conflict-free
#define NTHREADS 128    // 4 warps = exactly 1 per SMSP (balanced)

// Thread tile: 12 rows (6 f32x2 pairs) x 8 cols
//   rg = tid >> 4 (0..7)  -> r0 = 12*rg
//   cg = tid & 15 (0..15) -> c0 = 8*cg

#define SW_FLOATS  (DIN * NTILE)       // 32768 -> 128KB
#define SX_FLOATS  (DIN * XSTRIDE)     // 24576 ->  96KB
#define SMEM_BYTES ((SW_FLOATS + SX_FLOATS) * 4)   // 229376 B (fits 227KB max)

__device__ int g_cnt[NEXP];            // zero-init; gemm restores to 0
__device__ int g_done;                 // arrival counter, restored to 0
__device__ int g_rows[NEXP * BATCH];   // per-expert gather lists

// ---------------------------------------------------------------------------
__global__ void build_kernel(const float* __restrict__ onehot) {
    int b = blockIdx.x * blockDim.x + threadIdx.x;
    if (b >= BATCH) return;
    const float4* row = (const float4*)(onehot + (size_t)b * NEXP);
    int sel = 0;
#pragma unroll
    for (int j = 0; j < NEXP / 4; j++) {
        float4 v = row[j];
        if (v.x > 0.5f) sel = 4 * j + 0;
        if (v.y > 0.5f) sel = 4 * j + 1;
        if (v.z > 0.5f) sel = 4 * j + 2;
        if (v.w > 0.5f) sel = 4 * j + 3;
    }
    int p = atomicAdd(&g_cnt[sel], 1);
    g_rows[sel * BATCH + p] = b;
}

// packed fp32x2 FMA: d.lo += a.lo*b.lo ; d.hi += a.hi*b.hi
__device__ __forceinline__ void ffma2(unsigned long long& d,
                                      unsigned long long a,
                                      unsigned long long b) {
    asm("fma.rn.f32x2 %0, %1, %2, %0;" : "+l"(d) : "l"(a), "l"(b));
}
__device__ __forceinline__ unsigned long long dupf(float v) {
    unsigned long long r;
    asm("mov.b64 %0, {%1, %1};" : "=l"(r) : "f"(v));
    return r;
}
__device__ __forceinline__ float lo32(unsigned long long a) {
    return __uint_as_float((unsigned int)(a & 0xffffffffull));
}
__device__ __forceinline__ float hi32(unsigned long long a) {
    return __uint_as_float((unsigned int)(a >> 32));
}

// ---------------------------------------------------------------------------
// GEMM: blockIdx.y = expert, blockIdx.x = 128-col tile. 128 threads.
// ---------------------------------------------------------------------------
__global__ void __launch_bounds__(NTHREADS, 1)
gemm_kernel(const float* __restrict__ x,
            const float* __restrict__ W,
            const float* __restrict__ Bw,
            float* __restrict__ out) {
    extern __shared__ float smem[];
    float* s_w = smem;               // [k][c]  k*128 + c  (natural)
    float* s_x = smem + SW_FLOATS;   // [k][r]  k*96  + r  (transposed)

    const int e   = blockIdx.y;
    const int n0  = blockIdx.x * NTILE;
    const int tid = threadIdx.x;
    const int rg  = tid >> 4;        // 0..7
    const int cg  = tid & 15;        // 0..15
    const int r0  = 12 * rg;
    const int c0  = 8 * cg;

    const int  cnt  = g_cnt[e];                 // early: hide latency
    const int* rows = g_rows + e * BATCH;

    // bias for my 8 cols
    const float* bptr = Bw + (e << 8) + n0 + c0;
    float4 bias0 = *(const float4*)(bptr);
    float4 bias1 = *(const float4*)(bptr + 4);

    // --- stage W tile: 256k x 32 float4, coalesced, conflict-free ---
    {
        const float* We = W + ((size_t)e << 16) + n0;
#pragma unroll
        for (int it = 0; it < 64; it++) {
            int idx = tid + NTHREADS * it;      // 0..8191
            int k   = idx >> 5;
            int f4  = (idx & 31) << 2;
            float4 v = *(const float4*)(We + ((size_t)k << 8) + f4);
            *(float4*)(s_w + k * NTILE + f4) = v;
        }
    }

    for (int m0 = 0; m0 < cnt; m0 += MCHUNK) {
        const int nrows = min(MCHUNK, cnt - m0);
        __syncthreads();   // protect s_x from previous chunk's readers (noop 1st)

        // --- stage x transposed: s_x[k][r] = x[rows[m0+r]][k], r in [0,96) ---
        {
#pragma unroll
            for (int it = 0; it < 48; it++) {
                int idx = tid + NTHREADS * it;  // 0..6143 over 96 rows x 64 f4
                int r   = idx % MCHUNK;
                int kk  = idx / MCHUNK;         // float4 index 0..63
                int gr  = m0 + r;
                float4 v = (r < nrows)
                    ? ((const float4*)(x + ((size_t)rows[gr] << 8)))[kk]
                    : make_float4(0.f, 0.f, 0.f, 0.f);
                int k = kk << 2;
                s_x[(k + 0) * XSTRIDE + r] = v.x;   // bank r%32: conflict-free
                s_x[(k + 1) * XSTRIDE + r] = v.y;
                s_x[(k + 2) * XSTRIDE + r] = v.z;
                s_x[(k + 3) * XSTRIDE + r] = v.w;
            }
        }
        __syncthreads();

        if (r0 < nrows) {
            // --- register tile: 6 row-pairs x 8 cols ---
            unsigned long long acc[6][8];
#pragma unroll
            for (int p = 0; p < 6; p++)
#pragma unroll
                for (int j = 0; j < 8; j++) acc[p][j] = 0ull;

#pragma unroll 4
            for (int k = 0; k < DIN; k++) {
                const float* xk = s_x + k * XSTRIDE + r0;  // 16B aligned (48*rg)
                ulonglong2 xab = *(const ulonglong2*)(xk);      // pairs 0,1
                ulonglong2 xcd = *(const ulonglong2*)(xk + 4);  // pairs 2,3
                ulonglong2 xef = *(const ulonglong2*)(xk + 8);  // pairs 4,5
                const float* wk = s_w + k * NTILE + c0;
                float4 w0 = *(const float4*)(wk);
                float4 w1 = *(const float4*)(wk + 4);
                unsigned long long b0 = dupf(w0.x), b1 = dupf(w0.y);
                unsigned long long b2 = dupf(w0.z), b3 = dupf(w0.w);
                unsigned long long b4 = dupf(w1.x), b5 = dupf(w1.y);
                unsigned long long b6 = dupf(w1.z), b7 = dupf(w1.w);
                unsigned long long a0 = xab.x, a1 = xab.y;
                unsigned long long a2 = xcd.x, a3 = xcd.y;
                unsigned long long a4 = xef.x, a5 = xef.y;
                ffma2(acc[0][0], a0, b0); ffma2(acc[0][1], a0, b1);
                ffma2(acc[0][2], a0, b2); ffma2(acc[0][3], a0, b3);
                ffma2(acc[0][4], a0, b4); ffma2(acc[0][5], a0, b5);
                ffma2(acc[0][6], a0, b6); ffma2(acc[0][7], a0, b7);
                ffma2(acc[1][0], a1, b0); ffma2(acc[1][1], a1, b1);
                ffma2(acc[1][2], a1, b2); ffma2(acc[1][3], a1, b3);
                ffma2(acc[1][4], a1, b4); ffma2(acc[1][5], a1, b5);
                ffma2(acc[1][6], a1, b6); ffma2(acc[1][7], a1, b7);
                ffma2(acc[2][0], a2, b0); ffma2(acc[2][1], a2, b1);
                ffma2(acc[2][2], a2, b2); ffma2(acc[2][3], a2, b3);
                ffma2(acc[2][4], a2, b4); ffma2(acc[2][5], a2, b5);
                ffma2(acc[2][6], a2, b6); ffma2(acc[2][7], a2, b7);
                ffma2(acc[3][0], a3, b0); ffma2(acc[3][1], a3, b1);
                ffma2(acc[3][2], a3, b2); ffma2(acc[3][3], a3, b3);
                ffma2(acc[3][4], a3, b4); ffma2(acc[3][5], a3, b5);
                ffma2(acc[3][6], a3, b6); ffma2(acc[3][7], a3, b7);
                ffma2(acc[4][0], a4, b0); ffma2(acc[4][1], a4, b1);
                ffma2(acc[4][2], a4, b2); ffma2(acc[4][3], a4, b3);
                ffma2(acc[4][4], a4, b4); ffma2(acc[4][5], a4, b5);
                ffma2(acc[4][6], a4, b6); ffma2(acc[4][7], a4, b7);
                ffma2(acc[5][0], a5, b0); ffma2(acc[5][1], a5, b1);
                ffma2(acc[5][2], a5, b2); ffma2(acc[5][3], a5, b3);
                ffma2(acc[5][4], a5, b4); ffma2(acc[5][5], a5, b5);
                ffma2(acc[5][6], a5, b6); ffma2(acc[5][7], a5, b7);
            }

            // --- epilogue: 12 rows, 2 float4 stores per row ---
#pragma unroll
            for (int p = 0; p < 6; p++) {
                int m = m0 + r0 + 2 * p;
                if (m < cnt) {
                    float* op = out + ((size_t)rows[m] << 8) + n0 + c0;
                    float4 v0, v1;
                    v0.x = lo32(acc[p][0]) + bias0.x;
                    v0.y = lo32(acc[p][1]) + bias0.y;
                    v0.z = lo32(acc[p][2]) + bias0.z;
                    v0.w = lo32(acc[p][3]) + bias0.w;
                    v1.x = lo32(acc[p][4]) + bias1.x;
                    v1.y = lo32(acc[p][5]) + bias1.y;
                    v1.z = lo32(acc[p][6]) + bias1.z;
                    v1.w = lo32(acc[p][7]) + bias1.w;
                    *(float4*)(op) = v0;
                    *(float4*)(op + 4) = v1;
                }
                if (m + 1 < cnt) {
                    float* op = out + ((size_t)rows[m + 1] << 8) + n0 + c0;
                    float4 v0, v1;
                    v0.x = hi32(acc[p][0]) + bias0.x;
                    v0.y = hi32(acc[p][1]) + bias0.y;
                    v0.z = hi32(acc[p][2]) + bias0.z;
                    v0.w = hi32(acc[p][3]) + bias0.w;
                    v1.x = hi32(acc[p][4]) + bias1.x;
                    v1.y = hi32(acc[p][5]) + bias1.y;
                    v1.z = hi32(acc[p][6]) + bias1.z;
                    v1.w = hi32(acc[p][7]) + bias1.w;
                    *(float4*)(op) = v0;
                    *(float4*)(op + 4) = v1;
                }
            }
        }
    }

    // --- restore g_cnt / g_done to zero for the next graph replay ---
    __syncthreads();
    if (tid == 0) {
        __threadfence();
        int arrived = atomicAdd(&g_done, 1);
        if (arrived == (int)(gridDim.x * gridDim.y) - 1) {
#pragma unroll
            for (int i = 0; i < NEXP; i++) g_cnt[i] = 0;
            g_done = 0;
            __threadfence();
        }
    }
}

// ---------------------------------------------------------------------------
extern "C" void kernel_launch(void* const* d_in, const int* in_sizes, int n_in,
                              void* d_out, int out_size) {
    const float* x      = (const float*)d_in[0];
    const float* onehot = (const float*)d_in[1];
    const float* W      = (const float*)d_in[2];
    const float* Bw     = (const float*)d_in[3];
    float* out          = (float*)d_out;

    cudaFuncSetAttribute(gemm_kernel,
                         cudaFuncAttributeMaxDynamicSharedMemorySize,
                         SMEM_BYTES);

    build_kernel<<<BATCH / 256, 256>>>(onehot);
    gemm_kernel<<<dim3(DOUT / NTILE, NEXP), NTHREADS, SMEM_BYTES>>>(x, W, Bw, out);
}

// round 7
// speedup vs baseline: 1.3863x; 1.3863x over previous
#include <cuda_runtime.h>
#include <cuda_bf16.h>
#include <cstdint>

// Problem constants
#define BATCH 4096
#define DIN   256
#define DOUT  256
#define NEXP  64

#define NHALF 128        // N cols per CTA (2 CTAs per expert)
#define MCH   96         // M rows per chunk
#define NTHREADS 256

// smem byte offsets (dynamic)
#define S_WH   0                   // W hi: 4 k-tiles x [128 n][64 k] bf16 = 64KB
#define S_WL   65536               // W lo
#define S_XH   131072              // x hi: 4 k-tiles x [96 m][64 k] bf16 = 48KB
#define S_XL   180224              // x lo
#define S_BIAS 229376              // 128 floats
#define SMEM_BYTES 229888

#define WTILE 16384                // one W k-tile: 128 rows x 128B
#define XTILE 12288                // one x k-tile:  96 rows x 128B

// ---------------------------------------------------------------------------
__device__ int g_cnt[NEXP];            // zero-init; reset by gemm tail
__device__ int g_done;
__device__ int g_rows[NEXP * BATCH];
__device__ __nv_bfloat16 g_wth[NEXP * DIN * DOUT];   // [e][n][k] hi split
__device__ __nv_bfloat16 g_wtl[NEXP * DIN * DOUT];   // [e][n][k] lo split

// bf16 pack helpers: bf2(lo_f, hi_f) -> u32{hi16:bf16(hi_f), lo16:bf16(lo_f)}
__device__ __forceinline__ uint32_t bf2(float lo, float hi) {
    uint32_t r;
    asm("cvt.rn.bf16x2.f32 %0, %1, %2;" : "=r"(r) : "f"(hi), "f"(lo));
    return r;
}
__device__ __forceinline__ float bflo_f(uint32_t p) { return __uint_as_float(p << 16); }
__device__ __forceinline__ float bfhi_f(uint32_t p) { return __uint_as_float(p & 0xffff0000u); }

__device__ __forceinline__ uint32_t smem_to_u32(const void* p) {
    uint32_t a;
    asm("{ .reg .u64 t; cvta.to.shared.u64 t, %1; cvt.u32.u64 %0, t; }"
        : "=r"(a) : "l"(p));
    return a;
}

#define LDSM4(R, ADDR) \
    asm volatile("ldmatrix.sync.aligned.m8n8.x4.shared.b16 {%0,%1,%2,%3}, [%4];" \
        : "=r"((R)[0]), "=r"((R)[1]), "=r"((R)[2]), "=r"((R)[3]) : "r"(ADDR))

#define MMA16816(D, A, B0, B1) \
    asm volatile("mma.sync.aligned.m16n8k16.row.col.f32.bf16.bf16.f32 " \
        "{%0,%1,%2,%3}, {%4,%5,%6,%7}, {%8,%9}, {%0,%1,%2,%3};" \
        : "+r"((D)[0]), "+r"((D)[1]), "+r"((D)[2]), "+r"((D)[3]) \
        : "r"((A)[0]), "r"((A)[1]), "r"((A)[2]), "r"((A)[3]), "r"(B0), "r"(B1))

// ---------------------------------------------------------------------------
// Kernel 1: selector -> per-expert row lists
// ---------------------------------------------------------------------------
__global__ void build_kernel(const float* __restrict__ onehot) {
    int b = blockIdx.x * blockDim.x + threadIdx.x;
    if (b >= BATCH) return;
    const float4* row = (const float4*)(onehot + (size_t)b * NEXP);
    int sel = 0;
#pragma unroll
    for (int j = 0; j < NEXP / 4; j++) {
        float4 v = row[j];
        if (v.x > 0.5f) sel = 4 * j + 0;
        if (v.y > 0.5f) sel = 4 * j + 1;
        if (v.z > 0.5f) sel = 4 * j + 2;
        if (v.w > 0.5f) sel = 4 * j + 3;
    }
    int p = atomicAdd(&g_cnt[sel], 1);
    g_rows[sel * BATCH + p] = b;
}

// ---------------------------------------------------------------------------
// Kernel 2: W -> transposed bf16 hi/lo splits. grid (16 tiles, 64 experts).
// ---------------------------------------------------------------------------
__global__ void wsplit_kernel(const float* __restrict__ W) {
    __shared__ float s[64 * 65];
    const int e  = blockIdx.y;
    const int t  = blockIdx.x;
    const int k0 = (t & 3) * 64;
    const int n0 = (t >> 2) * 64;
    const int tid = threadIdx.x;
    const float* We = W + ((size_t)e << 16);

#pragma unroll
    for (int it = 0; it < 4; it++) {
        int idx = tid + 256 * it;
        int r  = idx >> 4;
        int c4 = (idx & 15) << 2;
        float4 v = *(const float4*)(We + (size_t)(k0 + r) * DOUT + n0 + c4);
        float* sp = s + r * 65 + c4;
        sp[0] = v.x; sp[1] = v.y; sp[2] = v.z; sp[3] = v.w;
    }
    __syncthreads();

#pragma unroll
    for (int it = 0; it < 4; it++) {
        int idx = tid + 256 * it;
        int rr = idx >> 4;                    // n within tile
        int c4 = (idx & 15) << 2;             // k quad
        float f0 = s[(c4 + 0) * 65 + rr];
        float f1 = s[(c4 + 1) * 65 + rr];
        float f2 = s[(c4 + 2) * 65 + rr];
        float f3 = s[(c4 + 3) * 65 + rr];
        uint32_t h0 = bf2(f0, f1);
        uint32_t h1 = bf2(f2, f3);
        uint32_t l0 = bf2(f0 - bflo_f(h0), f1 - bfhi_f(h0));
        uint32_t l1 = bf2(f2 - bflo_f(h1), f3 - bfhi_f(h1));
        size_t base = ((size_t)(e * DOUT + n0 + rr) << 8) + k0 + c4;
        *(uint2*)(&g_wth[base]) = make_uint2(h0, h1);
        *(uint2*)(&g_wtl[base]) = make_uint2(l0, l1);
    }
}

// ---------------------------------------------------------------------------
// Kernel 3: HMMA grouped GEMM. blockIdx.y = expert, blockIdx.x = n-half.
// 8 warps: warp grid 2m x 4n; warp tile 48m x 32n.
// 3-term bf16 split accumulated in fp32: xh*Wh + xh*Wl + xl*Wh.
// ---------------------------------------------------------------------------
__global__ void __launch_bounds__(NTHREADS, 1)
gemm_kernel(const float* __restrict__ x,
            const float* __restrict__ Bw,
            float* __restrict__ out) {
    extern __shared__ char smem[];
    const uint32_t sb = smem_to_u32(smem);
    float* s_bias = (float*)(smem + S_BIAS);

    const int tid  = threadIdx.x;
    const int lane = tid & 31;
    const int wid  = tid >> 5;
    const int e    = blockIdx.y;
    const int n0   = blockIdx.x * NHALF;

    if (tid < NHALF) s_bias[tid] = Bw[(e << 8) + n0 + tid];

    // --- stage W hi/lo, swizzled k-tiles ---
    {
        const __nv_bfloat16* wh = g_wth + (((size_t)e * DOUT + n0) << 8);
        const __nv_bfloat16* wl = g_wtl + (((size_t)e * DOUT + n0) << 8);
#pragma unroll
        for (int it = 0; it < 16; it++) {
            int u = tid + NTHREADS * it;    // 0..4095
            int n = u >> 5;                 // 0..127
            int c = u & 31;                 // 16B chunk (8 bf16)
            int kt = c >> 3, kb = c & 7;
            uint32_t dst = kt * WTILE + n * 128 + (uint32_t)((kb ^ (n & 7)) << 4);
            float4 vh = *(const float4*)(wh + ((size_t)n << 8) + (c << 3));
            float4 vl = *(const float4*)(wl + ((size_t)n << 8) + (c << 3));
            *(float4*)(smem + S_WH + dst) = vh;
            *(float4*)(smem + S_WL + dst) = vl;
        }
    }

    const int  cnt  = g_cnt[e];
    const int* rows = g_rows + e * BATCH;

    // warp/lane geometry
    const int mw0 = (wid >> 2) * 48;               // 0 or 48
    const int nw0 = (wid & 3) * 32;                // 0,32,64,96
    const int lm    = lane & 15;
    const int lhalf = lane >> 4;
    const int rlA   = lm & 7;                      // A row % 8 (mw0,16i ≡ 0 mod 8)
    const int nrow0 = nw0 + (lane & 7) + ((lane >> 4) << 3);
    const int rlB   = lane & 7;
    const int kb8   = (lane >> 3) & 1;

    uint32_t aBaseH[3], aBaseL[3];
#pragma unroll
    for (int i = 0; i < 3; i++) {
        uint32_t roff = (uint32_t)(mw0 + 16 * i + lm) * 128;
        aBaseH[i] = sb + S_XH + roff;
        aBaseL[i] = sb + S_XL + roff;
    }
    const uint32_t bBaseH = sb + S_WH + (uint32_t)nrow0 * 128;
    const uint32_t bBaseL = sb + S_WL + (uint32_t)nrow0 * 128;

    for (int m0 = 0; m0 < cnt; m0 += MCH) {
        const int nrows = min(MCH, cnt - m0);
        __syncthreads();   // previous chunk's mma done with s_x

        // --- stage x chunk: convert to bf16 hi/lo, swizzled k-tiles ---
#pragma unroll
        for (int it = 0; it < 12; it++) {
            int u = tid + NTHREADS * it;    // 0..3071
            int r = u >> 5;                 // 0..95
            int c = u & 31;                 // 8-float chunk
            int kt = c >> 3, kb = c & 7;
            float4 v0, v1;
            if (r < nrows) {
                const float4* xr = (const float4*)(x + ((size_t)rows[m0 + r] << 8));
                v0 = xr[2 * c]; v1 = xr[2 * c + 1];
            } else {
                v0 = make_float4(0.f, 0.f, 0.f, 0.f);
                v1 = v0;
            }
            uint32_t h0 = bf2(v0.x, v0.y), h1 = bf2(v0.z, v0.w);
            uint32_t h2 = bf2(v1.x, v1.y), h3 = bf2(v1.z, v1.w);
            uint32_t l0 = bf2(v0.x - bflo_f(h0), v0.y - bfhi_f(h0));
            uint32_t l1 = bf2(v0.z - bflo_f(h1), v0.w - bfhi_f(h1));
            uint32_t l2 = bf2(v1.x - bflo_f(h2), v1.y - bfhi_f(h2));
            uint32_t l3 = bf2(v1.z - bflo_f(h3), v1.w - bfhi_f(h3));
            uint32_t dst = kt * XTILE + r * 128 + (uint32_t)((kb ^ (r & 7)) << 4);
            *(uint4*)(smem + S_XH + dst) = make_uint4(h0, h1, h2, h3);
            *(uint4*)(smem + S_XL + dst) = make_uint4(l0, l1, l2, l3);
        }
        __syncthreads();

        // --- mma mainloop: D[3 m-frags][4 n-frags] fp32 ---
        uint32_t d[3][4][4];
#pragma unroll
        for (int i = 0; i < 3; i++)
#pragma unroll
            for (int j = 0; j < 4; j++)
#pragma unroll
                for (int q = 0; q < 4; q++) d[i][j][q] = 0u;

#pragma unroll 1
        for (int kt = 0; kt < 4; kt++) {
            const uint32_t aTile = (uint32_t)kt * XTILE;
            const uint32_t bTile = (uint32_t)kt * WTILE;
#pragma unroll
            for (int ks = 0; ks < 4; ks++) {
                uint32_t xorA = aTile + (uint32_t)((((2 * ks) + lhalf) ^ rlA) << 4);
                uint32_t xorB = bTile + (uint32_t)((((2 * ks) + kb8) ^ rlB) << 4);
                uint32_t ah[3][4], al[3][4];
#pragma unroll
                for (int i = 0; i < 3; i++) {
                    LDSM4(ah[i], aBaseH[i] + xorA);
                    LDSM4(al[i], aBaseL[i] + xorA);
                }
                uint32_t bh[8], bl[8];
                LDSM4(bh, bBaseH + xorB);
                LDSM4(bh + 4, bBaseH + 2048 + xorB);   // n-rows +16
                LDSM4(bl, bBaseL + xorB);
                LDSM4(bl + 4, bBaseL + 2048 + xorB);
#pragma unroll
                for (int i = 0; i < 3; i++)
#pragma unroll
                    for (int j = 0; j < 4; j++) {
                        MMA16816(d[i][j], ah[i], bh[2 * j], bh[2 * j + 1]);
                        MMA16816(d[i][j], ah[i], bl[2 * j], bl[2 * j + 1]);
                        MMA16816(d[i][j], al[i], bh[2 * j], bh[2 * j + 1]);
                    }
            }
        }

        // --- epilogue: add bias, scatter rows ---
#pragma unroll
        for (int i = 0; i < 3; i++) {
            int rlo = mw0 + 16 * i + (lane >> 2);
#pragma unroll
            for (int half = 0; half < 2; half++) {
                int m = m0 + rlo + 8 * half;
                if (m < cnt) {
                    float* op = out + ((size_t)rows[m] << 8) + n0;
#pragma unroll
                    for (int j = 0; j < 4; j++) {
                        int c = nw0 + 8 * j + 2 * (lane & 3);
                        float2 b = *(float2*)(s_bias + c);
                        float2 v;
                        v.x = __uint_as_float(d[i][j][2 * half + 0]) + b.x;
                        v.y = __uint_as_float(d[i][j][2 * half + 1]) + b.y;
                        *(float2*)(op + c) = v;
                    }
                }
            }
        }
    }

    // --- reset counters for next graph replay ---
    if (tid == 0) {
        __threadfence();
        int arrived = atomicAdd(&g_done, 1);
        if (arrived == (int)(gridDim.x * gridDim.y) - 1) {
#pragma unroll
            for (int i = 0; i < NEXP; i++) g_cnt[i] = 0;
            g_done = 0;
            __threadfence();
        }
    }
}

// ---------------------------------------------------------------------------
extern "C" void kernel_launch(void* const* d_in, const int* in_sizes, int n_in,
                              void* d_out, int out_size) {
    const float* x      = (const float*)d_in[0];
    const float* onehot = (const float*)d_in[1];
    const float* W      = (const float*)d_in[2];
    const float* Bw     = (const float*)d_in[3];
    float* out          = (float*)d_out;

    cudaFuncSetAttribute(gemm_kernel,
                         cudaFuncAttributeMaxDynamicSharedMemorySize,
                         SMEM_BYTES);

    build_kernel<<<BATCH / 256, 256>>>(onehot);
    wsplit_kernel<<<dim3(16, NEXP), 256>>>(W);
    gemm_kernel<<<dim3(DOUT / NHALF, NEXP), NTHREADS, SMEM_BYTES>>>(x, Bw, out);
}

// round 8
// speedup vs baseline: 2.1631x; 1.5604x over previous
#include <cuda_runtime.h>
#include <cuda_bf16.h>
#include <cstdint>

// Problem constants
#define BATCH 4096
#define DIN   256
#define DOUT  256
#define NEXP  64

#define NHALF 128        // N cols per CTA (2 CTAs per expert)
#define MCH   96         // M rows per chunk
#define NTHREADS 256
#define RCAP  192        // row-list capacity (max expert load ~96 w.h.p.)

// smem byte offsets (dynamic)
#define S_WH   0                   // W hi: [256 k][128 n] bf16, 256B rows = 64KB
#define S_WL   65536               // W lo
#define S_XH   131072              // x hi: [96 m][256 k] bf16, 512B rows = 48KB
#define S_XL   180224              // x lo
#define S_BIAS 229376              // 128 floats
#define S_ROWS 229888              // RCAP ints
#define S_CNT  230656
#define SMEM_BYTES 230912

// ---------------------------------------------------------------------------
__device__ __forceinline__ uint32_t bf2(float lo, float hi) {
    uint32_t r;
    asm("cvt.rn.bf16x2.f32 %0, %1, %2;" : "=r"(r) : "f"(hi), "f"(lo));
    return r;
}
__device__ __forceinline__ float bflo_f(uint32_t p) { return __uint_as_float(p << 16); }
__device__ __forceinline__ float bfhi_f(uint32_t p) { return __uint_as_float(p & 0xffff0000u); }

__device__ __forceinline__ uint32_t smem_to_u32(const void* p) {
    uint32_t a;
    asm("{ .reg .u64 t; cvta.to.shared.u64 t, %1; cvt.u32.u64 %0, t; }"
        : "=r"(a) : "l"(p));
    return a;
}

#define LDSM4(R, ADDR) \
    asm volatile("ldmatrix.sync.aligned.m8n8.x4.shared.b16 {%0,%1,%2,%3}, [%4];" \
        : "=r"((R)[0]), "=r"((R)[1]), "=r"((R)[2]), "=r"((R)[3]) : "r"(ADDR))

#define LDSM4T(R, ADDR) \
    asm volatile("ldmatrix.sync.aligned.m8n8.x4.trans.shared.b16 {%0,%1,%2,%3}, [%4];" \
        : "=r"((R)[0]), "=r"((R)[1]), "=r"((R)[2]), "=r"((R)[3]) : "r"(ADDR))

#define MMA16816(D, A, B0, B1) \
    asm volatile("mma.sync.aligned.m16n8k16.row.col.f32.bf16.bf16.f32 " \
        "{%0,%1,%2,%3}, {%4,%5,%6,%7}, {%8,%9}, {%0,%1,%2,%3};" \
        : "+r"((D)[0]), "+r"((D)[1]), "+r"((D)[2]), "+r"((D)[3]) \
        : "r"((A)[0]), "r"((A)[1]), "r"((A)[2]), "r"((A)[3]), "r"(B0), "r"(B1))

// ---------------------------------------------------------------------------
// Fused kernel. blockIdx.y = expert, blockIdx.x = n-half.
// 8 warps: warp grid 2m x 4n; warp tile 48m x 32n.
// 3-term bf16 split accumulated in fp32: xh*Wh + xh*Wl + xl*Wh.
// ---------------------------------------------------------------------------
__global__ void __launch_bounds__(NTHREADS, 1)
gemm_kernel(const float* __restrict__ x,
            const float* __restrict__ onehot,
            const float* __restrict__ W,
            const float* __restrict__ Bw,
            float* __restrict__ out) {
    extern __shared__ char smem[];
    const uint32_t sb = smem_to_u32(smem);
    float* s_bias = (float*)(smem + S_BIAS);
    int*   s_rows = (int*)(smem + S_ROWS);
    int*   s_cnt  = (int*)(smem + S_CNT);

    const int tid  = threadIdx.x;
    const int lane = tid & 31;
    const int wid  = tid >> 5;
    const int e    = blockIdx.y;
    const int n0   = blockIdx.x * NHALF;

    if (tid == 0) *s_cnt = 0;

    // --- issue selector-column scan loads (strided; L2-shared across CTAs) ---
    float f[16];
#pragma unroll
    for (int j = 0; j < 16; j++)
        f[j] = onehot[((size_t)(tid + 256 * j) << 6) + e];

    // --- stage W tile [256k][128n]: fp32 gmem -> bf16 hi/lo smem, swizzled ---
    {
        const float* We = W + ((size_t)e << 16) + n0;   // W[e][k][n]
#pragma unroll
        for (int it = 0; it < 16; it++) {
            int u  = tid + NTHREADS * it;   // 0..4095
            int k  = u >> 4;
            int nc = u & 15;                // 8-float chunk within row
            const float* src = We + ((size_t)k << 8) + (nc << 3);
            float4 v0 = *(const float4*)(src);
            float4 v1 = *(const float4*)(src + 4);
            uint32_t h0 = bf2(v0.x, v0.y), h1 = bf2(v0.z, v0.w);
            uint32_t h2 = bf2(v1.x, v1.y), h3 = bf2(v1.z, v1.w);
            uint32_t l0 = bf2(v0.x - bflo_f(h0), v0.y - bfhi_f(h0));
            uint32_t l1 = bf2(v0.z - bflo_f(h1), v0.w - bfhi_f(h1));
            uint32_t l2 = bf2(v1.x - bflo_f(h2), v1.y - bfhi_f(h2));
            uint32_t l3 = bf2(v1.z - bflo_f(h3), v1.w - bfhi_f(h3));
            uint32_t gsw = (uint32_t)((nc & 8) | ((nc & 7) ^ (k & 7)));
            uint32_t dst = ((uint32_t)k << 8) + (gsw << 4);
            *(uint4*)(smem + S_WH + dst) = make_uint4(h0, h1, h2, h3);
            *(uint4*)(smem + S_WL + dst) = make_uint4(l0, l1, l2, l3);
        }
    }

    if (tid < NHALF) s_bias[tid] = Bw[(e << 8) + n0 + tid];

    __syncthreads();   // s_cnt init visible

    // --- compact this expert's rows (order irrelevant: per-row math identical) ---
#pragma unroll
    for (int j = 0; j < 16; j++) {
        if (f[j] > 0.5f) {
            int p = atomicAdd(s_cnt, 1);
            if (p < RCAP) s_rows[p] = tid + 256 * j;
        }
    }
    __syncthreads();   // s_rows/s_cnt + W smem ready

    const int cnt = *s_cnt;

    // warp/lane geometry
    const int mw0 = (wid >> 2) * 48;               // 0 or 48
    const int nw0 = (wid & 3) * 32;                // 0,32,64,96
    const int lm    = lane & 15;
    const int lhalf = lane >> 4;
    const int l7    = lane & 7;

    // A fragment base addresses (row = mw0+16i+lm, 512B rows)
    uint32_t aBaseH[3], aBaseL[3];
#pragma unroll
    for (int i = 0; i < 3; i++) {
        uint32_t roff = (uint32_t)(mw0 + 16 * i + lm) << 9;
        aBaseH[i] = sb + S_XH + roff;
        aBaseL[i] = sb + S_XL + roff;
    }
    // B fragment: kRow = 16*ks + lm (256B rows); two n-chunk pairs
    const uint32_t bRowOff = (uint32_t)lm << 8;
    const int ncA = (wid & 3) * 4 + lhalf;
    const int ncB = ncA + 2;
    const uint32_t gswBA = (uint32_t)((ncA & 8) | ((ncA & 7) ^ l7)) << 4;
    const uint32_t gswBB = (uint32_t)((ncB & 8) | ((ncB & 7) ^ l7)) << 4;
    const uint32_t bBaseH = sb + S_WH + bRowOff;
    const uint32_t bBaseL = sb + S_WL + bRowOff;

    for (int m0 = 0; m0 < cnt; m0 += MCH) {
        const int nrows = min(MCH, cnt - m0);

        // --- stage x chunk [96m][256k]: fp32 -> bf16 hi/lo, swizzled ---
#pragma unroll
        for (int it = 0; it < 12; it++) {
            int u = tid + NTHREADS * it;    // 0..3071
            int r = u >> 5;                 // 0..95
            int c = u & 31;                 // 8-float chunk
            float4 v0, v1;
            if (r < nrows) {
                const float4* xr = (const float4*)(x + ((size_t)s_rows[m0 + r] << 8));
                v0 = xr[2 * c]; v1 = xr[2 * c + 1];
            } else {
                v0 = make_float4(0.f, 0.f, 0.f, 0.f);
                v1 = v0;
            }
            uint32_t h0 = bf2(v0.x, v0.y), h1 = bf2(v0.z, v0.w);
            uint32_t h2 = bf2(v1.x, v1.y), h3 = bf2(v1.z, v1.w);
            uint32_t l0 = bf2(v0.x - bflo_f(h0), v0.y - bfhi_f(h0));
            uint32_t l1 = bf2(v0.z - bflo_f(h1), v0.w - bfhi_f(h1));
            uint32_t l2 = bf2(v1.x - bflo_f(h2), v1.y - bfhi_f(h2));
            uint32_t l3 = bf2(v1.z - bflo_f(h3), v1.w - bfhi_f(h3));
            uint32_t gsw = (uint32_t)((c & 24) | ((c & 7) ^ (r & 7)));
            uint32_t dst = ((uint32_t)r << 9) + (gsw << 4);
            *(uint4*)(smem + S_XH + dst) = make_uint4(h0, h1, h2, h3);
            *(uint4*)(smem + S_XL + dst) = make_uint4(l0, l1, l2, l3);
        }
        __syncthreads();

        // --- mma mainloop: D[3 m-frags][4 n-frags] fp32 ---
        uint32_t d[3][4][4];
#pragma unroll
        for (int i = 0; i < 3; i++)
#pragma unroll
            for (int j = 0; j < 4; j++)
#pragma unroll
                for (int q = 0; q < 4; q++) d[i][j][q] = 0u;

#pragma unroll 2
        for (int ks = 0; ks < 16; ks++) {
            int gA = 2 * ks + lhalf;   // A k-granule 0..31
            uint32_t swA = (uint32_t)((gA & 24) | ((gA & 7) ^ l7)) << 4;
            uint32_t bK = (uint32_t)ks << 12;   // 16 k-rows * 256B

            uint32_t ah[3][4], al[3][4];
#pragma unroll
            for (int i = 0; i < 3; i++) {
                LDSM4(ah[i], aBaseH[i] + swA);
                LDSM4(al[i], aBaseL[i] + swA);
            }
            uint32_t bh[8], bl[8];
            LDSM4T(bh,     bBaseH + bK + gswBA);
            LDSM4T(bh + 4, bBaseH + bK + gswBB);
            LDSM4T(bl,     bBaseL + bK + gswBA);
            LDSM4T(bl + 4, bBaseL + bK + gswBB);

#pragma unroll
            for (int i = 0; i < 3; i++)
#pragma unroll
                for (int j = 0; j < 4; j++) {
                    MMA16816(d[i][j], ah[i], bh[2 * j], bh[2 * j + 1]);
                    MMA16816(d[i][j], ah[i], bl[2 * j], bl[2 * j + 1]);
                    MMA16816(d[i][j], al[i], bh[2 * j], bh[2 * j + 1]);
                }
        }

        // --- epilogue: add bias, scatter rows ---
#pragma unroll
        for (int i = 0; i < 3; i++) {
            int rlo = mw0 + 16 * i + (lane >> 2);
#pragma unroll
            for (int half = 0; half < 2; half++) {
                int m = m0 + rlo + 8 * half;
                if (m < cnt) {
                    float* op = out + ((size_t)s_rows[m] << 8) + n0;
#pragma unroll
                    for (int j = 0; j < 4; j++) {
                        int c = nw0 + 8 * j + 2 * (lane & 3);
                        float2 b = *(float2*)(s_bias + c);
                        float2 v;
                        v.x = __uint_as_float(d[i][j][2 * half + 0]) + b.x;
                        v.y = __uint_as_float(d[i][j][2 * half + 1]) + b.y;
                        *(float2*)(op + c) = v;
                    }
                }
            }
        }
        __syncthreads();   // before next chunk overwrites s_x
    }
}

// ---------------------------------------------------------------------------
extern "C" void kernel_launch(void* const* d_in, const int* in_sizes, int n_in,
                              void* d_out, int out_size) {
    const float* x      = (const float*)d_in[0];
    const float* onehot = (const float*)d_in[1];
    const float* W      = (const float*)d_in[2];
    const float* Bw     = (const float*)d_in[3];
    float* out          = (float*)d_out;

    cudaFuncSetAttribute(gemm_kernel,
                         cudaFuncAttributeMaxDynamicSharedMemorySize,
                         SMEM_BYTES);

    gemm_kernel<<<dim3(DOUT / NHALF, NEXP), NTHREADS, SMEM_BYTES>>>(
        x, onehot, W, Bw, out);
}